// round 14
// baseline (speedup 1.0000x reference)
#include <cuda_runtime.h>
#include <math_constants.h>
#include <cstdint>

// ---------------- static device scratch (no runtime allocation) ----------------
// Flat-row layouts: 3136 = 16 batches x 196 tokens. cumc = {0,64,192,448}.
__device__ __align__(16) float g_K     [4u*3136*960];    // [h][3136][960]
__device__ __align__(16) float g_V     [4u*3136*960];    // [h][3136][960]
__device__ __align__(16) float g_Q     [4u*3136*960];    // per-branch [4][3136][c] regions
__device__ __align__(16) float g_scores[64u*960*960];    // per-branch [64z][c][960] regions
__device__ __align__(16) float g_ctxm  [16u*196*960];    // per-branch [16][196][c] regions
__device__ float g_partial[4*64*32*2];
__device__ int   g_rowmaxi[64*960];                      // rows: rmbase[br] + z*c + d

__device__ __forceinline__ int f2ord(float f) {
    int i = __float_as_int(f);
    return i >= 0 ? i : i ^ 0x7fffffff;
}
__device__ __forceinline__ float ord2f(int i) {
    return __int_as_float(i >= 0 ? i : i ^ 0x7fffffff);
}

#define BM 128
#define BN 128
#define BK 8
#define PAD 4
#define NJ 8

// ---------------- job table for merged GEMM launches ------------------------------
struct Jobs {
    const float* A[NJ]; const float* B[NJ]; float* C[NJ];
    long sAh[NJ], sAb[NJ], sBh[NJ], sBb[NJ], sCh[NJ], sCb[NJ];
    int  lda[NJ], ldb[NJ], ldc[NJ], M[NJ], N[NJ], K[NJ];
    float alpha[NJ];
    int  nx[NJ];      // tiles along N
    int  bx0[NJ];     // cumulative blockIdx.x start (unused: INT_MAX)
    int  rmoff[NJ];   // row-max base (row units)
};

// ---------------------------------------------------------------------------------
// C[M,N] = alpha * opA * opB  — proven round-11 scalar SGEMM core (BK=8).
//   LAYA==0 : A is [M,K] row-major          LAYA==1 : A is [K,M] row-major
//   LAYB==0 : B is [N,K] row-major (B^T)    LAYB==1 : B is [K,N] row-major
// STATS: epilogue row-max atomics + block sum/sumsq partials (InstanceNorm)
// CTX  : epilogue atomicAdd into transposed ctxm[b][n][d] (fused head-mean)
// per-z operand offset = (z&3)*sh + (z>>2)*sb
// ---------------------------------------------------------------------------------
template<int LAYA, int LAYB, bool STATS, bool CTX>
__device__ __forceinline__ void gemm_core(const Jobs& J, int br, int local, int zz)
{
    __shared__ float As[BK][BM + PAD];
    __shared__ float Bs[BK][BN + PAD];
    const float* A = J.A[br];
    const float* B = J.B[br];
    float*       C = J.C[br];
    const int lda = J.lda[br], ldb = J.ldb[br], ldc = J.ldc[br];
    const int M = J.M[br], N = J.N[br], K = J.K[br];
    const float alpha = J.alpha[br];
    const int h = zz & 3, bb_ = zz >> 2;
    A += (long)h * J.sAh[br] + (long)bb_ * J.sAb[br];
    B += (long)h * J.sBh[br] + (long)bb_ * J.sBb[br];
    C += (long)h * J.sCh[br] + (long)bb_ * J.sCb[br];
    const int nx = J.nx[br];
    const int row0 = (local / nx) * BM, col0 = (local % nx) * BN;

    const int tid = threadIdx.x;
    const int tx = tid & 15, ty = tid >> 4;

    // A tile loader
    const int arow  = tid >> 1;          // LAYA==0: tile row (m)
    const int akseg = (tid & 1) * 4;
    const int agr   = row0 + arow;
    const int akk   = tid >> 5;          // LAYA==1: tile row (k)
    const int am    = (tid & 31) * 4;
    // B tile loader
    const int brow  = tid >> 1;          // LAYB==0
    const int bkseg = (tid & 1) * 4;
    const int bkk   = tid >> 5;          // LAYB==1
    const int bn    = (tid & 31) * 4;

    float acc[8][8];
#pragma unroll
    for (int i = 0; i < 8; i++)
#pragma unroll
        for (int j = 0; j < 8; j++) acc[i][j] = 0.f;

    const int KT = (K + BK - 1) / BK;
    float4 av, bv;

    auto loadA = [&](int k0) {
        float4 v = make_float4(0.f, 0.f, 0.f, 0.f);
        if (LAYA == 0) {
            int gk = k0 + akseg;
            if (agr < M && gk < K)
                v = *reinterpret_cast<const float4*>(A + (size_t)agr * lda + gk);
        } else {
            int gk = k0 + akk, gm = row0 + am;
            if (gk < K && gm < M)
                v = *reinterpret_cast<const float4*>(A + (size_t)gk * lda + gm);
        }
        return v;
    };
    auto loadB = [&](int k0) {
        float4 v = make_float4(0.f, 0.f, 0.f, 0.f);
        if (LAYB == 0) {
            int gk = k0 + bkseg, gn = col0 + brow;
            if (gn < N && gk < K)
                v = *reinterpret_cast<const float4*>(B + (size_t)gn * ldb + gk);
        } else {
            int gk = k0 + bkk, gn = col0 + bn;
            if (gk < K && gn < N)
                v = *reinterpret_cast<const float4*>(B + (size_t)gk * ldb + gn);
        }
        return v;
    };
    auto storeS = [&]() {
        if (LAYA == 0) {
            As[akseg + 0][arow] = av.x; As[akseg + 1][arow] = av.y;
            As[akseg + 2][arow] = av.z; As[akseg + 3][arow] = av.w;
        } else {
            *reinterpret_cast<float4*>(&As[akk][am]) = av;
        }
        if (LAYB == 0) {
            Bs[bkseg + 0][brow] = bv.x; Bs[bkseg + 1][brow] = bv.y;
            Bs[bkseg + 2][brow] = bv.z; Bs[bkseg + 3][brow] = bv.w;
        } else {
            *reinterpret_cast<float4*>(&Bs[bkk][bn]) = bv;
        }
    };
    auto compute = [&]() {
#pragma unroll
        for (int kk = 0; kk < BK; kk++) {
            float a[8], bq[8];
            *reinterpret_cast<float4*>(a)      = *reinterpret_cast<const float4*>(&As[kk][ty * 8]);
            *reinterpret_cast<float4*>(a + 4)  = *reinterpret_cast<const float4*>(&As[kk][ty * 8 + 4]);
            *reinterpret_cast<float4*>(bq)     = *reinterpret_cast<const float4*>(&Bs[kk][tx * 8]);
            *reinterpret_cast<float4*>(bq + 4) = *reinterpret_cast<const float4*>(&Bs[kk][tx * 8 + 4]);
#pragma unroll
            for (int i = 0; i < 8; i++)
#pragma unroll
                for (int j = 0; j < 8; j++)
                    acc[i][j] = fmaf(a[i], bq[j], acc[i][j]);
        }
    };

    av = loadA(0); bv = loadB(0);
    storeS();
    __syncthreads();
    for (int t = 1; t < KT; t++) {
        av = loadA(t * BK); bv = loadB(t * BK);
        compute();
        __syncthreads();
        storeS();
        __syncthreads();
    }
    compute();

#pragma unroll
    for (int i = 0; i < 8; i++)
#pragma unroll
        for (int j = 0; j < 8; j++) acc[i][j] *= alpha;

    if (CTX) {
        // Transposed fused head-mean: ctxm[(b·196+n)·c + d] += acc (alpha=0.25)
#pragma unroll
        for (int j = 0; j < 8; j++) {
            int gc = col0 + tx * 8 + j;          // n
            if (gc >= N) continue;
            float* cp = C + (size_t)gc * ldc + row0 + ty * 8;
#pragma unroll
            for (int i = 0; i < 8; i++) {
                int gr = row0 + ty * 8 + i;      // d
                if (gr < M) atomicAdd(cp + i, acc[i][j]);
            }
        }
    } else {
#pragma unroll
        for (int i = 0; i < 8; i++) {
            int gr = row0 + ty * 8 + i;
            if (gr >= M) continue;
            int gc0 = col0 + tx * 8;
            float* cp = C + (size_t)gr * ldc + gc0;
            if (gc0 + 7 < N) {
                *reinterpret_cast<float4*>(cp)     = *reinterpret_cast<float4*>(&acc[i][0]);
                *reinterpret_cast<float4*>(cp + 4) = *reinterpret_cast<float4*>(&acc[i][4]);
            } else {
#pragma unroll
                for (int j = 0; j < 8; j++)
                    if (gc0 + j < N) cp[j] = acc[i][j];
            }
        }
    }

    if (STATS) {
        float lsum = 0.f, lsq = 0.f;
#pragma unroll
        for (int i = 0; i < 8; i++) {
            float rm = -CUDART_INF_F;
            int gr = row0 + ty * 8 + i;
#pragma unroll
            for (int j = 0; j < 8; j++) {
                int gc = col0 + tx * 8 + j;
                if (gc < N) {
                    float v = acc[i][j];
                    lsum += v; lsq += v * v;
                    rm = fmaxf(rm, v);
                }
            }
#pragma unroll
            for (int m = 1; m < 16; m <<= 1)
                rm = fmaxf(rm, __shfl_xor_sync(0xffffffffu, rm, m, 16));
            if (tx == 0 && gr < M)
                atomicMax(&g_rowmaxi[J.rmoff[br] + zz * M + gr], f2ord(rm));
        }
        __shared__ float s1[256], s2[256];
        s1[tid] = lsum; s2[tid] = lsq;
        __syncthreads();
        for (int s = 128; s > 0; s >>= 1) {
            if (tid < s) { s1[tid] += s1[tid + s]; s2[tid] += s2[tid + s]; }
            __syncthreads();
        }
        if (tid == 0) {
            int pb = ((br * 64 + zz) * 32 + local) * 2;
            g_partial[pb] = s1[0];
            g_partial[pb + 1] = s2[0];
        }
    }
}

__device__ __forceinline__ int pick_branch(const Jobs& J, int bx) {
    int br = 0;
#pragma unroll
    for (int i = 1; i < NJ; i++)
        if (bx >= J.bx0[i]) br = i;
    return br;
}

__global__ __launch_bounds__(256, 2) void k_gemm_abT(Jobs J) {
    int bx = blockIdx.x, br = pick_branch(J, bx);
    gemm_core<0, 0, false, false>(J, br, bx - J.bx0[br], blockIdx.z);
}
__global__ __launch_bounds__(256, 2) void k_gemm_aTb_stats(Jobs J) {
    int bx = blockIdx.x, br = pick_branch(J, bx);
    gemm_core<1, 1, true, false>(J, br, bx - J.bx0[br], blockIdx.z);
}
__global__ __launch_bounds__(256, 2) void k_gemm_ctx(Jobs J) {
    int bx = blockIdx.x, br = pick_branch(J, bx);
    gemm_core<0, 0, false, true>(J, br, bx - J.bx0[br], blockIdx.z);
}

// ---------------- small kernels ----------------------------------------------------
// init rowmax sentinels + zero ctxm (atomic accumulation target; graph-replay safe)
__global__ void k_init()
{
    int i = blockIdx.x * 256 + threadIdx.x;
    if (i < 64 * 960) g_rowmaxi[i] = 0x80000000;
    int j = i - 64 * 960;
    if (j >= 0 && j < 16 * 196 * 960) g_ctxm[j] = 0.f;
}

// One block per score row: p <- softmax((p - mean)*invstd) computed as
// exp(p*invstd - max*invstd)/sum (InstanceNorm mean cancels by shift-invariance).
// invstd computed inline from the stats-GEMM partials (warp 0).
__global__ __launch_bounds__(256) void k_probs()
{
    int idx = blockIdx.x;                   // global row in [0, 61440)
    int br = (idx >= 4096) + (idx >= 12288) + (idx >= 28672);
    const int cs[4]   = {64, 128, 256, 512};
    const int base[4] = {0, 4096, 12288, 28672};
    const int nbk[4]  = {8, 8, 16, 32};
    const long soff[4] = {0, 64L*64*960, 64L*192*960, 64L*448*960};
    int local = idx - base[br];
    int c = cs[br];
    int z = local / c;

    __shared__ float s_is;
    int t = threadIdx.x;
    if (t < 32) {
        float sum = 0.f, sq = 0.f;
        if (t < nbk[br]) {
            int pb = ((br * 64 + z) * 32 + t) * 2;
            sum = g_partial[pb];
            sq  = g_partial[pb + 1];
        }
#pragma unroll
        for (int m = 16; m > 0; m >>= 1) {
            sum += __shfl_xor_sync(0xffffffffu, sum, m);
            sq  += __shfl_xor_sync(0xffffffffu, sq,  m);
        }
        if (t == 0) {
            float n = (float)c * 960.f;
            float mu = sum / n;
            s_is = rsqrtf(sq / n - mu * mu + 1e-5f);
        }
    }
    __syncthreads();
    float is  = s_is;
    float off = ord2f(g_rowmaxi[idx]) * is;
    float* p = g_scores + soff[br] + (long)local * 960;

    bool v3 = (t + 768) < 960;
    float e0 = __expf(p[t]       * is - off);
    float e1 = __expf(p[t + 256] * is - off);
    float e2 = __expf(p[t + 512] * is - off);
    float e3 = v3 ? __expf(p[t + 768] * is - off) : 0.f;

    __shared__ float sh[256];
    sh[t] = e0 + e1 + e2 + e3;
    __syncthreads();
    for (int s = 128; s > 0; s >>= 1) {
        if (t < s) sh[t] += sh[t + s];
        __syncthreads();
    }
    float rinv = 1.f / sh[0];
    p[t]       = e0 * rinv;
    p[t + 256] = e1 * rinv;
    p[t + 512] = e2 * rinv;
    if (v3) p[t + 768] = e3 * rinv;
}

// ---------------- launch -------------------------------------------------------------
extern "C" void kernel_launch(void* const* d_in, const int* in_sizes, int n_in,
                              void* d_out, int out_size)
{
    (void)in_sizes; (void)n_in; (void)out_size;
    const float* emb[4]  = {(const float*)d_in[0], (const float*)d_in[1],
                            (const float*)d_in[2], (const float*)d_in[3]};
    const float* emb_all = (const float*)d_in[4];
    const float* Wq[4]   = {(const float*)d_in[5], (const float*)d_in[6],
                            (const float*)d_in[7], (const float*)d_in[8]};
    const float* Wk      = (const float*)d_in[9];
    const float* Wv      = (const float*)d_in[10];
    const float* Wo[4]   = {(const float*)d_in[11], (const float*)d_in[12],
                            (const float*)d_in[13], (const float*)d_in[14]};
    float* out = (float*)d_out;

    float *pK, *pV, *pQ, *pSc, *pCm;
    cudaGetSymbolAddress((void**)&pK,  g_K);
    cudaGetSymbolAddress((void**)&pV,  g_V);
    cudaGetSymbolAddress((void**)&pQ,  g_Q);
    cudaGetSymbolAddress((void**)&pSc, g_scores);
    cudaGetSymbolAddress((void**)&pCm, g_ctxm);

    const int   Cs[4]    = {64, 128, 256, 512};
    const int   cumc[4]  = {0, 64, 192, 448};
    const int   my[4]    = {1, 1, 2, 4};            // ceil(c/128)
    const int   rmbase[4]= {0, 4096, 12288, 28672};
    const int   offs[4]  = {0, 16*196*64, 16*196*(64+128), 16*196*(64+128+256)};
    const float SCALE    = 0.03227486121839514f;    // 1/sqrt(960)
    const int   IMAXI    = 0x7fffffff;

    // init rowmax + zero ctxm: 61440 + 3010560 elements
    k_init<<<(64 * 960 + 16 * 196 * 960 + 255) / 256, 256>>>();

    // ---- ONE merged projection launch: K, V, Q0..Q3 (all per-h, M=3136) ----
    {
        Jobs J = {};
        // job0: K[h][3136][960] = emb_all_flat @ Wk[h]^T
        J.A[0]=emb_all; J.sAh[0]=0; J.sAb[0]=0; J.lda[0]=960;
        J.B[0]=Wk; J.sBh[0]=960L*960; J.sBb[0]=0; J.ldb[0]=960;
        J.C[0]=pK; J.sCh[0]=3136L*960; J.sCb[0]=0; J.ldc[0]=960;
        J.M[0]=3136; J.N[0]=960; J.K[0]=960; J.alpha[0]=1.f; J.nx[0]=8; J.bx0[0]=0;
        // job1: V[h][3136][960] = emb_all_flat @ Wv[h]^T
        J.A[1]=emb_all; J.sAh[1]=0; J.sAb[1]=0; J.lda[1]=960;
        J.B[1]=Wv; J.sBh[1]=960L*960; J.sBb[1]=0; J.ldb[1]=960;
        J.C[1]=pV; J.sCh[1]=3136L*960; J.sCb[1]=0; J.ldc[1]=960;
        J.M[1]=3136; J.N[1]=960; J.K[1]=960; J.alpha[1]=1.f; J.nx[1]=8; J.bx0[1]=200;
        // jobs 2..5: Q_br[h][3136][c] = emb_br_flat @ Wq_br[h]^T
        int bx = 400;
        for (int br = 0; br < 4; br++) {
            long c = Cs[br];
            int s = 2 + br;
            J.A[s]=emb[br]; J.sAh[s]=0; J.sAb[s]=0; J.lda[s]=(int)c;
            J.B[s]=Wq[br];  J.sBh[s]=c*c; J.sBb[s]=0; J.ldb[s]=(int)c;
            J.C[s]=pQ + 4L*3136*cumc[br];
            J.sCh[s]=3136L*c; J.sCb[s]=0; J.ldc[s]=(int)c;
            J.M[s]=3136; J.N[s]=(int)c; J.K[s]=(int)c; J.alpha[s]=1.f;
            int nxq = (Cs[br] + 127) / 128;          // {1,1,2,4}
            J.nx[s]=nxq; J.bx0[s]=bx; bx += 25 * nxq;
        }
        for (int s = 6; s < NJ; s++) J.bx0[s] = IMAXI;
        k_gemm_abT<<<dim3(600, 1, 4), 256>>>(J);     // bx total = 600
    }

    // ---- merged scores GEMM (A^T form) + stats epilogue (4 jobs, z=64) ----
    {
        Jobs J = {};
        int bx = 0;
        for (int br = 0; br < 4; br++) {
            long c = Cs[br];
            J.A[br]=pQ + 4L*3136*cumc[br];           // [h][3136][c], slice [196,c]
            J.sAh[br]=3136L*c; J.sAb[br]=196L*c; J.lda[br]=(int)c;
            J.B[br]=pK;                               // [h][3136][960], slice [196,960]
            J.sBh[br]=3136L*960; J.sBb[br]=196L*960; J.ldb[br]=960;
            J.C[br]=pSc + 64L*960*cumc[br];
            J.sCh[br]=c*960; J.sCb[br]=4L*c*960; J.ldc[br]=960;
            J.M[br]=(int)c; J.N[br]=960; J.K[br]=196; J.alpha[br]=SCALE;
            J.nx[br]=8; J.bx0[br]=bx; J.rmoff[br]=rmbase[br]; bx += 8 * my[br];
        }
        for (int s = 4; s < NJ; s++) J.bx0[s] = IMAXI;
        k_gemm_aTb_stats<<<dim3(64, 1, 64), 256>>>(J);
    }

    k_probs<<<61440, 256>>>();

    // ---- merged ctx GEMM with fused head-mean epilogue (4 jobs, z=64) ----
    // ctxm[b][n][d] += 0.25 * (probs[z] @ Vslice^T)[d][n]   via atomicAdd
    {
        Jobs J = {};
        int bx = 0;
        for (int br = 0; br < 4; br++) {
            long c = Cs[br];
            J.A[br]=pSc + 64L*960*cumc[br];
            J.sAh[br]=c*960; J.sAb[br]=4L*c*960; J.lda[br]=960;
            J.B[br]=pV;                               // [h][3136][960], slice [196,960]
            J.sBh[br]=3136L*960; J.sBb[br]=196L*960; J.ldb[br]=960;
            J.C[br]=pCm + 16L*196*cumc[br];           // [b][196][c] (transposed epilogue)
            J.sCh[br]=0; J.sCb[br]=196L*c; J.ldc[br]=(int)c;
            J.M[br]=(int)c; J.N[br]=196; J.K[br]=960; J.alpha[br]=0.25f;
            J.nx[br]=2; J.bx0[br]=bx; bx += 2 * my[br];
        }
        for (int s = 4; s < NJ; s++) J.bx0[s] = IMAXI;
        k_gemm_ctx<<<dim3(16, 1, 64), 256>>>(J);
    }

    // ---- merged output projections (4 jobs, z=1) ----
    {
        Jobs J = {};
        int bx = 0;
        for (int br = 0; br < 4; br++) {
            long c = Cs[br];
            J.A[br]=pCm + 16L*196*cumc[br];
            J.sAh[br]=0; J.sAb[br]=0; J.lda[br]=(int)c;
            J.B[br]=Wo[br]; J.sBh[br]=0; J.sBb[br]=0; J.ldb[br]=(int)c;
            J.C[br]=out + offs[br]; J.sCh[br]=0; J.sCb[br]=0; J.ldc[br]=(int)c;
            J.M[br]=16*196; J.N[br]=(int)c; J.K[br]=(int)c; J.alpha[br]=1.f;
            int nxo = (Cs[br] + 127) / 128;
            J.nx[br]=nxo; J.bx0[br]=bx; bx += nxo * 25;
        }
        for (int s = 4; s < NJ; s++) J.bx0[s] = IMAXI;
        k_gemm_abT<<<dim3(200, 1, 1), 256>>>(J);
    }
}

// round 15
// speedup vs baseline: 1.0231x; 1.0231x over previous
#include <cuda_runtime.h>
#include <math_constants.h>
#include <cstdint>

// ---------------- static device scratch (no runtime allocation) ----------------
// Flat-row layouts: 3136 = 16 batches x 196 tokens. cumc = {0,64,192,448}.
__device__ __align__(16) float g_K     [4u*3136*960];    // [h][3136][960]
__device__ __align__(16) float g_V     [4u*3136*960];    // [h][3136][960]
__device__ __align__(16) float g_Q     [4u*3136*960];    // per-branch [4][3136][c] regions
__device__ __align__(16) float g_scores[64u*960*960];    // per-branch [64z][c][960] regions
__device__ __align__(16) float g_ctx   [64u*960*196];    // per-branch [64z][c][196] regions
__device__ __align__(16) float g_ctxm  [16u*196*960];    // per-branch [16][196][c] regions
__device__ float g_partial[4*64*32*2];
__device__ int   g_rowmaxi[64*960];                      // rows: rmbase[br] + z*c + d

__device__ __forceinline__ int f2ord(float f) {
    int i = __float_as_int(f);
    return i >= 0 ? i : i ^ 0x7fffffff;
}
__device__ __forceinline__ float ord2f(int i) {
    return __int_as_float(i >= 0 ? i : i ^ 0x7fffffff);
}

#define BM 128
#define BN 128
#define BK 8
#define PAD 4
#define NJ 8

// ---------------- job table for merged GEMM launches ------------------------------
struct Jobs {
    const float* A[NJ]; const float* B[NJ]; float* C[NJ];
    long sAh[NJ], sAb[NJ], sBh[NJ], sBb[NJ], sCh[NJ], sCb[NJ];
    int  lda[NJ], ldb[NJ], ldc[NJ], M[NJ], N[NJ], K[NJ];
    float alpha[NJ];
    int  nx[NJ];      // tiles along N
    int  bx0[NJ];     // cumulative blockIdx.x start (unused: INT_MAX)
    int  rmoff[NJ];   // row-max base (row units)
};

// ---------------------------------------------------------------------------------
// C[M,N] = alpha * opA * opB  — proven round-11 scalar SGEMM core (BK=8).
//   LAYA==0 : A is [M,K] row-major          LAYA==1 : A is [K,M] row-major
//   LAYB==0 : B is [N,K] row-major (B^T)    LAYB==1 : B is [K,N] row-major
// STATS: epilogue row-max atomics + block sum/sumsq partials (InstanceNorm)
// per-z operand offset = (z&3)*sh + (z>>2)*sb
// ---------------------------------------------------------------------------------
template<int LAYA, int LAYB, bool STATS>
__device__ __forceinline__ void gemm_core(const Jobs& J, int br, int local, int zz)
{
    __shared__ float As[BK][BM + PAD];
    __shared__ float Bs[BK][BN + PAD];
    const float* A = J.A[br];
    const float* B = J.B[br];
    float*       C = J.C[br];
    const int lda = J.lda[br], ldb = J.ldb[br], ldc = J.ldc[br];
    const int M = J.M[br], N = J.N[br], K = J.K[br];
    const float alpha = J.alpha[br];
    const int h = zz & 3, bb_ = zz >> 2;
    A += (long)h * J.sAh[br] + (long)bb_ * J.sAb[br];
    B += (long)h * J.sBh[br] + (long)bb_ * J.sBb[br];
    C += (long)h * J.sCh[br] + (long)bb_ * J.sCb[br];
    const int nx = J.nx[br];
    const int row0 = (local / nx) * BM, col0 = (local % nx) * BN;

    const int tid = threadIdx.x;
    const int tx = tid & 15, ty = tid >> 4;

    // A tile loader
    const int arow  = tid >> 1;          // LAYA==0: tile row (m)
    const int akseg = (tid & 1) * 4;
    const int agr   = row0 + arow;
    const int akk   = tid >> 5;          // LAYA==1: tile row (k)
    const int am    = (tid & 31) * 4;
    // B tile loader
    const int brow  = tid >> 1;          // LAYB==0
    const int bkseg = (tid & 1) * 4;
    const int bkk   = tid >> 5;          // LAYB==1
    const int bn    = (tid & 31) * 4;

    float acc[8][8];
#pragma unroll
    for (int i = 0; i < 8; i++)
#pragma unroll
        for (int j = 0; j < 8; j++) acc[i][j] = 0.f;

    const int KT = (K + BK - 1) / BK;
    float4 av, bv;

    auto loadA = [&](int k0) {
        float4 v = make_float4(0.f, 0.f, 0.f, 0.f);
        if (LAYA == 0) {
            int gk = k0 + akseg;
            if (agr < M && gk < K)
                v = *reinterpret_cast<const float4*>(A + (size_t)agr * lda + gk);
        } else {
            int gk = k0 + akk, gm = row0 + am;
            if (gk < K && gm < M)
                v = *reinterpret_cast<const float4*>(A + (size_t)gk * lda + gm);
        }
        return v;
    };
    auto loadB = [&](int k0) {
        float4 v = make_float4(0.f, 0.f, 0.f, 0.f);
        if (LAYB == 0) {
            int gk = k0 + bkseg, gn = col0 + brow;
            if (gn < N && gk < K)
                v = *reinterpret_cast<const float4*>(B + (size_t)gn * ldb + gk);
        } else {
            int gk = k0 + bkk, gn = col0 + bn;
            if (gk < K && gn < N)
                v = *reinterpret_cast<const float4*>(B + (size_t)gk * ldb + gn);
        }
        return v;
    };
    auto storeS = [&]() {
        if (LAYA == 0) {
            As[akseg + 0][arow] = av.x; As[akseg + 1][arow] = av.y;
            As[akseg + 2][arow] = av.z; As[akseg + 3][arow] = av.w;
        } else {
            *reinterpret_cast<float4*>(&As[akk][am]) = av;
        }
        if (LAYB == 0) {
            Bs[bkseg + 0][brow] = bv.x; Bs[bkseg + 1][brow] = bv.y;
            Bs[bkseg + 2][brow] = bv.z; Bs[bkseg + 3][brow] = bv.w;
        } else {
            *reinterpret_cast<float4*>(&Bs[bkk][bn]) = bv;
        }
    };
    auto compute = [&]() {
#pragma unroll
        for (int kk = 0; kk < BK; kk++) {
            float a[8], bq[8];
            *reinterpret_cast<float4*>(a)      = *reinterpret_cast<const float4*>(&As[kk][ty * 8]);
            *reinterpret_cast<float4*>(a + 4)  = *reinterpret_cast<const float4*>(&As[kk][ty * 8 + 4]);
            *reinterpret_cast<float4*>(bq)     = *reinterpret_cast<const float4*>(&Bs[kk][tx * 8]);
            *reinterpret_cast<float4*>(bq + 4) = *reinterpret_cast<const float4*>(&Bs[kk][tx * 8 + 4]);
#pragma unroll
            for (int i = 0; i < 8; i++)
#pragma unroll
                for (int j = 0; j < 8; j++)
                    acc[i][j] = fmaf(a[i], bq[j], acc[i][j]);
        }
    };

    av = loadA(0); bv = loadB(0);
    storeS();
    __syncthreads();
    for (int t = 1; t < KT; t++) {
        av = loadA(t * BK); bv = loadB(t * BK);
        compute();
        __syncthreads();
        storeS();
        __syncthreads();
    }
    compute();

#pragma unroll
    for (int i = 0; i < 8; i++)
#pragma unroll
        for (int j = 0; j < 8; j++) acc[i][j] *= alpha;

#pragma unroll
    for (int i = 0; i < 8; i++) {
        int gr = row0 + ty * 8 + i;
        if (gr >= M) continue;
        int gc0 = col0 + tx * 8;
        float* cp = C + (size_t)gr * ldc + gc0;
        if (gc0 + 7 < N) {
            *reinterpret_cast<float4*>(cp)     = *reinterpret_cast<float4*>(&acc[i][0]);
            *reinterpret_cast<float4*>(cp + 4) = *reinterpret_cast<float4*>(&acc[i][4]);
        } else {
#pragma unroll
            for (int j = 0; j < 8; j++)
                if (gc0 + j < N) cp[j] = acc[i][j];
        }
    }

    if (STATS) {
        float lsum = 0.f, lsq = 0.f;
#pragma unroll
        for (int i = 0; i < 8; i++) {
            float rm = -CUDART_INF_F;
            int gr = row0 + ty * 8 + i;
#pragma unroll
            for (int j = 0; j < 8; j++) {
                int gc = col0 + tx * 8 + j;
                if (gc < N) {
                    float v = acc[i][j];
                    lsum += v; lsq += v * v;
                    rm = fmaxf(rm, v);
                }
            }
#pragma unroll
            for (int m = 1; m < 16; m <<= 1)
                rm = fmaxf(rm, __shfl_xor_sync(0xffffffffu, rm, m, 16));
            if (tx == 0 && gr < M)
                atomicMax(&g_rowmaxi[J.rmoff[br] + zz * M + gr], f2ord(rm));
        }
        __shared__ float s1[256], s2[256];
        s1[tid] = lsum; s2[tid] = lsq;
        __syncthreads();
        for (int s = 128; s > 0; s >>= 1) {
            if (tid < s) { s1[tid] += s1[tid + s]; s2[tid] += s2[tid + s]; }
            __syncthreads();
        }
        if (tid == 0) {
            int pb = ((br * 64 + zz) * 32 + local) * 2;
            g_partial[pb] = s1[0];
            g_partial[pb + 1] = s2[0];
        }
    }
}

__device__ __forceinline__ int pick_branch(const Jobs& J, int bx) {
    int br = 0;
#pragma unroll
    for (int i = 1; i < NJ; i++)
        if (bx >= J.bx0[i]) br = i;
    return br;
}

__global__ __launch_bounds__(256, 2) void k_gemm_abT(Jobs J) {
    int bx = blockIdx.x, br = pick_branch(J, bx);
    gemm_core<0, 0, false>(J, br, bx - J.bx0[br], blockIdx.z);
}
__global__ __launch_bounds__(256, 2) void k_gemm_aTb_stats(Jobs J) {
    int bx = blockIdx.x, br = pick_branch(J, bx);
    gemm_core<1, 1, true>(J, br, bx - J.bx0[br], blockIdx.z);
}

// ---------------- small kernels ----------------------------------------------------
__global__ void k_initmax()
{
    int i = blockIdx.x * 256 + threadIdx.x;
    if (i < 64 * 960) g_rowmaxi[i] = 0x80000000;
}

// One block per score row: p <- softmax((p - mean)*invstd) computed as
// exp(p*invstd - max*invstd)/sum (InstanceNorm mean cancels by shift-invariance).
// invstd computed inline from the stats-GEMM partials (warp 0); float4 streaming.
__global__ __launch_bounds__(256) void k_probs()
{
    int idx = blockIdx.x;                   // global row in [0, 61440)
    int br = (idx >= 4096) + (idx >= 12288) + (idx >= 28672);
    const int cs[4]   = {64, 128, 256, 512};
    const int base[4] = {0, 4096, 12288, 28672};
    const int nbk[4]  = {8, 8, 16, 32};
    const long soff[4] = {0, 64L*64*960, 64L*192*960, 64L*448*960};
    int local = idx - base[br];
    int c = cs[br];
    int z = local / c;

    __shared__ float s_is;
    int t = threadIdx.x;
    if (t < 32) {
        float sum = 0.f, sq = 0.f;
        if (t < nbk[br]) {
            int pb = ((br * 64 + z) * 32 + t) * 2;
            sum = g_partial[pb];
            sq  = g_partial[pb + 1];
        }
#pragma unroll
        for (int m = 16; m > 0; m >>= 1) {
            sum += __shfl_xor_sync(0xffffffffu, sum, m);
            sq  += __shfl_xor_sync(0xffffffffu, sq,  m);
        }
        if (t == 0) {
            float n = (float)c * 960.f;
            float mu = sum / n;
            s_is = rsqrtf(sq / n - mu * mu + 1e-5f);
        }
    }
    __syncthreads();
    float is  = s_is;
    float off = ord2f(g_rowmaxi[idx]) * is;
    float* p = g_scores + soff[br] + (long)local * 960;

    // one float4 per thread: 240 active lanes cover the 960-float row
    float4 e = make_float4(0.f, 0.f, 0.f, 0.f);
    bool act = t < 240;
    if (act) {
        float4 v = *reinterpret_cast<const float4*>(p + t * 4);
        e.x = __expf(v.x * is - off);
        e.y = __expf(v.y * is - off);
        e.z = __expf(v.z * is - off);
        e.w = __expf(v.w * is - off);
    }
    __shared__ float sh[256];
    sh[t] = e.x + e.y + e.z + e.w;
    __syncthreads();
    for (int s = 128; s > 0; s >>= 1) {
        if (t < s) sh[t] += sh[t + s];
        __syncthreads();
    }
    float rinv = 1.f / sh[0];
    if (act) {
        e.x *= rinv; e.y *= rinv; e.z *= rinv; e.w *= rinv;
        *reinterpret_cast<float4*>(p + t * 4) = e;
    }
}

// ctxm[b][n][d] = 0.25 * sum_h ctx[b*4+h][d][n]  (all branches via blockIdx.y)
__global__ void k_meanT_all()
{
    __shared__ float t[32][33];
    int by = blockIdx.y;
    int br = (by >= 2) + (by >= 6) + (by >= 14);
    const int cs[4]    = {64, 128, 256, 512};
    const int ybase[4] = {0, 2, 6, 14};
    const long ctxoff[4] = {0, 64L*64*196, 64L*192*196, 64L*448*196};
    const long cmoff[4]  = {0, 16L*196*64, 16L*196*192, 16L*196*448};
    int c = cs[br];
    int b  = blockIdx.z;
    int d0 = (by - ybase[br]) * 32, n0 = blockIdx.x * 32;
    const float* ctx = g_ctx + ctxoff[br];
    float* cm = g_ctxm + cmoff[br];
    int tx = threadIdx.x, ty = threadIdx.y;
    for (int i = ty; i < 32; i += 8) {
        int d = d0 + i, n = n0 + tx;
        float s = 0.f;
        if (n < 196) {
            for (int hh = 0; hh < 4; hh++)
                s += ctx[((size_t)(b * 4 + hh) * c + d) * 196 + n];
        }
        t[i][tx] = 0.25f * s;
    }
    __syncthreads();
    for (int i = ty; i < 32; i += 8) {
        int n = n0 + i, d = d0 + tx;
        if (n < 196) cm[((size_t)b * 196 + n) * c + d] = t[tx][i];
    }
}

// ---------------- launch -------------------------------------------------------------
extern "C" void kernel_launch(void* const* d_in, const int* in_sizes, int n_in,
                              void* d_out, int out_size)
{
    (void)in_sizes; (void)n_in; (void)out_size;
    const float* emb[4]  = {(const float*)d_in[0], (const float*)d_in[1],
                            (const float*)d_in[2], (const float*)d_in[3]};
    const float* emb_all = (const float*)d_in[4];
    const float* Wq[4]   = {(const float*)d_in[5], (const float*)d_in[6],
                            (const float*)d_in[7], (const float*)d_in[8]};
    const float* Wk      = (const float*)d_in[9];
    const float* Wv      = (const float*)d_in[10];
    const float* Wo[4]   = {(const float*)d_in[11], (const float*)d_in[12],
                            (const float*)d_in[13], (const float*)d_in[14]};
    float* out = (float*)d_out;

    float *pK, *pV, *pQ, *pSc, *pCx, *pCm;
    cudaGetSymbolAddress((void**)&pK,  g_K);
    cudaGetSymbolAddress((void**)&pV,  g_V);
    cudaGetSymbolAddress((void**)&pQ,  g_Q);
    cudaGetSymbolAddress((void**)&pSc, g_scores);
    cudaGetSymbolAddress((void**)&pCx, g_ctx);
    cudaGetSymbolAddress((void**)&pCm, g_ctxm);

    const int   Cs[4]    = {64, 128, 256, 512};
    const int   cumc[4]  = {0, 64, 192, 448};
    const int   my[4]    = {1, 1, 2, 4};            // ceil(c/128)
    const int   rmbase[4]= {0, 4096, 12288, 28672};
    const int   offs[4]  = {0, 16*196*64, 16*196*(64+128), 16*196*(64+128+256)};
    const float SCALE    = 0.03227486121839514f;    // 1/sqrt(960)
    const int   IMAXI    = 0x7fffffff;

    k_initmax<<<(64 * 960 + 255) / 256, 256>>>();

    // ---- ONE merged projection launch: K, V, Q0..Q3 (all per-h, M=3136) ----
    {
        Jobs J = {};
        // job0: K[h][3136][960] = emb_all_flat @ Wk[h]^T
        J.A[0]=emb_all; J.sAh[0]=0; J.sAb[0]=0; J.lda[0]=960;
        J.B[0]=Wk; J.sBh[0]=960L*960; J.sBb[0]=0; J.ldb[0]=960;
        J.C[0]=pK; J.sCh[0]=3136L*960; J.sCb[0]=0; J.ldc[0]=960;
        J.M[0]=3136; J.N[0]=960; J.K[0]=960; J.alpha[0]=1.f; J.nx[0]=8; J.bx0[0]=0;
        // job1: V[h][3136][960] = emb_all_flat @ Wv[h]^T
        J.A[1]=emb_all; J.sAh[1]=0; J.sAb[1]=0; J.lda[1]=960;
        J.B[1]=Wv; J.sBh[1]=960L*960; J.sBb[1]=0; J.ldb[1]=960;
        J.C[1]=pV; J.sCh[1]=3136L*960; J.sCb[1]=0; J.ldc[1]=960;
        J.M[1]=3136; J.N[1]=960; J.K[1]=960; J.alpha[1]=1.f; J.nx[1]=8; J.bx0[1]=200;
        // jobs 2..5: Q_br[h][3136][c] = emb_br_flat @ Wq_br[h]^T
        int bx = 400;
        for (int br = 0; br < 4; br++) {
            long c = Cs[br];
            int s = 2 + br;
            J.A[s]=emb[br]; J.sAh[s]=0; J.sAb[s]=0; J.lda[s]=(int)c;
            J.B[s]=Wq[br];  J.sBh[s]=c*c; J.sBb[s]=0; J.ldb[s]=(int)c;
            J.C[s]=pQ + 4L*3136*cumc[br];
            J.sCh[s]=3136L*c; J.sCb[s]=0; J.ldc[s]=(int)c;
            J.M[s]=3136; J.N[s]=(int)c; J.K[s]=(int)c; J.alpha[s]=1.f;
            int nxq = (Cs[br] + 127) / 128;          // {1,1,2,4}
            J.nx[s]=nxq; J.bx0[s]=bx; bx += 25 * nxq;
        }
        for (int s = 6; s < NJ; s++) J.bx0[s] = IMAXI;
        k_gemm_abT<<<dim3(600, 1, 4), 256>>>(J);     // bx total = 600
    }

    // ---- merged scores GEMM (A^T form) + stats epilogue (4 jobs, z=64) ----
    {
        Jobs J = {};
        int bx = 0;
        for (int br = 0; br < 4; br++) {
            long c = Cs[br];
            J.A[br]=pQ + 4L*3136*cumc[br];           // [h][3136][c], slice [196,c]
            J.sAh[br]=3136L*c; J.sAb[br]=196L*c; J.lda[br]=(int)c;
            J.B[br]=pK;                               // [h][3136][960], slice [196,960]
            J.sBh[br]=3136L*960; J.sBb[br]=196L*960; J.ldb[br]=960;
            J.C[br]=pSc + 64L*960*cumc[br];
            J.sCh[br]=c*960; J.sCb[br]=4L*c*960; J.ldc[br]=960;
            J.M[br]=(int)c; J.N[br]=960; J.K[br]=196; J.alpha[br]=SCALE;
            J.nx[br]=8; J.bx0[br]=bx; J.rmoff[br]=rmbase[br]; bx += 8 * my[br];
        }
        for (int s = 4; s < NJ; s++) J.bx0[s] = IMAXI;
        k_gemm_aTb_stats<<<dim3(64, 1, 64), 256>>>(J);
    }

    k_probs<<<61440, 256>>>();

    // ---- merged ctx GEMM: C = probs * Vslice^T (4 jobs, z=64) ----
    {
        Jobs J = {};
        int bx = 0;
        for (int br = 0; br < 4; br++) {
            long c = Cs[br];
            J.A[br]=pSc + 64L*960*cumc[br];
            J.sAh[br]=c*960; J.sAb[br]=4L*c*960; J.lda[br]=960;
            J.B[br]=pV;                               // [h][3136][960], slice [196,960]
            J.sBh[br]=3136L*960; J.sBb[br]=196L*960; J.ldb[br]=960;
            J.C[br]=pCx + 64L*196*cumc[br];
            J.sCh[br]=c*196; J.sCb[br]=4L*c*196; J.ldc[br]=196;
            J.M[br]=(int)c; J.N[br]=196; J.K[br]=960; J.alpha[br]=1.f;
            J.nx[br]=2; J.bx0[br]=bx; bx += 2 * my[br];
        }
        for (int s = 4; s < NJ; s++) J.bx0[s] = IMAXI;
        k_gemm_abT<<<dim3(16, 1, 64), 256>>>(J);
    }

    k_meanT_all<<<dim3(7, 30, 16), dim3(32, 8)>>>();

    // ---- merged output projections (4 jobs, z=1) ----
    {
        Jobs J = {};
        int bx = 0;
        for (int br = 0; br < 4; br++) {
            long c = Cs[br];
            J.A[br]=pCm + 16L*196*cumc[br];
            J.sAh[br]=0; J.sAb[br]=0; J.lda[br]=(int)c;
            J.B[br]=Wo[br]; J.sBh[br]=0; J.sBb[br]=0; J.ldb[br]=(int)c;
            J.C[br]=out + offs[br]; J.sCh[br]=0; J.sCb[br]=0; J.ldc[br]=(int)c;
            J.M[br]=16*196; J.N[br]=(int)c; J.K[br]=(int)c; J.alpha[br]=1.f;
            int nxo = (Cs[br] + 127) / 128;
            J.nx[br]=nxo; J.bx0[br]=bx; bx += nxo * 25;
        }
        for (int s = 4; s < NJ; s++) J.bx0[s] = IMAXI;
        k_gemm_abT<<<dim3(200, 1, 1), 256>>>(J);
    }
}